// round 14
// baseline (speedup 1.0000x reference)
#include <cuda_runtime.h>
#include <cuda.h>
#include <cuda_bf16.h>
#include <cstdint>

// ---------------- problem constants ----------------
#define B_   8
#define K_   288
#define L_   16384
#define O_   64
#define NT   256
#define LT   256         // l-tile per CTA-iteration
#define CH   16          // k per chunk = one k-step
#define NCH  18
#define NKS  18
#define NSTG 4
#define NTILES  512      // total l-tiles (B_ * L_/LT)
#define GRID    296      // persistent CTAs (148 SMs x occ 2)

#define STAGE_B   16384                     // 8 segs x 16 k-rows x 128B (swizzled)
#define CHUNK_TX  16384
#define OFF_MBAR  (NSTG * STAGE_B)          // 65536
#define SMEM_BYTES (OFF_MBAR + 64)

// ---------------- prep outputs ----------------
__device__ uint2  g_wfrag[NKS * 8 * 32];    // B fragments [ks][nt][lane]
__device__ float4 g_wb4[O_ / 2];            // (w2,bias) pairs

__global__ void gauss_prep_kernel(const float* __restrict__ w,
                                  const float* __restrict__ bias) {
    int t = threadIdx.x;
    if (blockIdx.x < NKS) {
        int ks   = blockIdx.x;
        int nt   = t >> 5;
        int lane = t & 31;
        int k = ks * 16 + (lane & 3) * 2;
        int o = nt * 8 + (lane >> 2);
        __nv_bfloat162 b0 = __floats2bfloat162_rn(w[k * O_ + o], w[(k + 1) * O_ + o]);
        __nv_bfloat162 b1 = __floats2bfloat162_rn(w[(k + 8) * O_ + o], w[(k + 9) * O_ + o]);
        uint2 v;
        v.x = *reinterpret_cast<uint32_t*>(&b0);
        v.y = *reinterpret_cast<uint32_t*>(&b1);
        g_wfrag[(ks * 8 + nt) * 32 + lane] = v;
    } else {
        __shared__ float s_w2[O_];
        int o   = t >> 2;
        int sub = t & 3;
        float s = 0.f;
        #pragma unroll 8
        for (int k = sub; k < K_; k += 4) { float v = w[k * O_ + o]; s = fmaf(v, v, s); }
        s += __shfl_xor_sync(0xFFFFFFFF, s, 1);
        s += __shfl_xor_sync(0xFFFFFFFF, s, 2);
        if (sub == 0) s_w2[o] = s;
        __syncthreads();
        if (t < O_ / 2) {
            float4 r;
            r.x = s_w2[2 * t];     r.y = bias[2 * t];
            r.z = s_w2[2 * t + 1]; r.w = bias[2 * t + 1];
            g_wb4[t] = r;
        }
    }
}

// ---------------- PTX helpers ----------------
__device__ __forceinline__ uint32_t smem_u32(const void* p) {
    return (uint32_t)__cvta_generic_to_shared(p);
}
__device__ __forceinline__ void mbar_init(uint32_t mbar, uint32_t cnt) {
    asm volatile("mbarrier.init.shared.b64 [%0], %1;" :: "r"(mbar), "r"(cnt) : "memory");
}
__device__ __forceinline__ void mbar_expect_tx(uint32_t mbar, uint32_t bytes) {
    asm volatile("mbarrier.arrive.expect_tx.shared.b64 _, [%0], %1;"
                 :: "r"(mbar), "r"(bytes) : "memory");
}
__device__ __forceinline__ void mbar_wait(uint32_t mbar, uint32_t parity) {
    uint32_t done;
    asm volatile(
        "{\n\t.reg .pred p;\n\t"
        "mbarrier.try_wait.parity.acquire.cta.shared::cta.b64 p, [%1], %2;\n\t"
        "selp.b32 %0, 1, 0, p;\n\t}"
        : "=r"(done) : "r"(mbar), "r"(parity) : "memory");
    if (!done) {
        asm volatile(
            "{\n\t.reg .pred P1;\n\t"
            "WAIT_LOOP_%=:\n\t"
            "mbarrier.try_wait.parity.acquire.cta.shared::cta.b64 P1, [%0], %1, 0x989680;\n\t"
            "@P1 bra.uni WAIT_DONE_%=;\n\t"
            "bra.uni WAIT_LOOP_%=;\n\t"
            "WAIT_DONE_%=:\n\t}"
            :: "r"(mbar), "r"(parity) : "memory");
    }
}
__device__ __forceinline__ void tma_load_3d(uint32_t dst, const CUtensorMap* tmap,
                                            int cx, int cy, int cz, uint32_t mbar) {
    asm volatile(
        "cp.async.bulk.tensor.3d.shared::cta.global.tile.mbarrier::complete_tx::bytes "
        "[%0], [%1, {%2, %3, %4}], [%5];"
        :: "r"(dst), "l"(tmap), "r"(cx), "r"(cy), "r"(cz), "r"(mbar) : "memory");
}
__device__ __forceinline__ uint32_t packbf(float lo, float hi) {
    __nv_bfloat162 h = __floats2bfloat162_rn(lo, hi);
    return *reinterpret_cast<uint32_t*>(&h);
}
__device__ __forceinline__ void mma16816(float* c,
                                         uint32_t a0, uint32_t a1, uint32_t a2, uint32_t a3,
                                         uint32_t b0, uint32_t b1) {
    asm volatile(
        "mma.sync.aligned.m16n8k16.row.col.f32.bf16.bf16.f32 "
        "{%0,%1,%2,%3}, {%4,%5,%6,%7}, {%8,%9}, {%0,%1,%2,%3};"
        : "+f"(c[0]), "+f"(c[1]), "+f"(c[2]), "+f"(c[3])
        : "r"(a0), "r"(a1), "r"(a2), "r"(a3), "r"(b0), "r"(b1));
}

extern __shared__ __align__(1024) char g_sm[];

__global__ __launch_bounds__(NT, 2)
void gauss_main_kernel(const __grid_constant__ CUtensorMap tmap,
                       const float* __restrict__ gamma_p,
                       float* __restrict__ out) {
    const int t     = threadIdx.x;
    const int warp  = t >> 5;
    const int lane  = t & 31;
    const int cta   = blockIdx.x;          // 0..295

    const int ntile = (cta + GRID < NTILES) ? 2 : 1;
    const int NC    = NCH * ntile;         // flat chunk stream across tiles

    const uint32_t stg_base = smem_u32(g_sm);
    const uint32_t mbar0    = stg_base + OFF_MBAR;

    const int kc  = (lane & 3) * 2;
    const int llo = lane >> 2;
    const int w512 = warp * 512;           // warp's seg slice (floats) per stage

    if (t == 0) {
        #pragma unroll
        for (int s = 0; s < NSTG; ++s) mbar_init(mbar0 + s * 8, 1);
    }
    __syncthreads();

    float acc[2][8][4];
    #pragma unroll
    for (int s = 0; s < 2; ++s)
        #pragma unroll
        for (int i = 0; i < 8; ++i)
            #pragma unroll
            for (int j = 0; j < 4; ++j) acc[s][i][j] = 0.f;
    float x2a[2][2] = {{0.f, 0.f}, {0.f, 0.f}};

    const float gamma = __ldg(gamma_p);

    // chunk g -> tile coords
    //   tile = cta + (g/NCH)*GRID ; ks = g%NCH ; b = tile>>6 ; l0 = (tile&63)*LT
    // prologue: chunks 0..2 (all within tile 0 since NCH=18 > 3)
    if (warp == 0) {
        const int tile0 = cta;
        const int b0_   = tile0 >> 6;
        const int l00   = (tile0 & 63) * LT;
        #pragma unroll
        for (int p = 0; p < NSTG - 1; ++p) {
            uint32_t mb = mbar0 + p * 8;
            if (lane == 0) mbar_expect_tx(mb, CHUNK_TX);
            __syncwarp();
            if (lane < 8)
                tma_load_3d(stg_base + p * STAGE_B + lane * 2048,
                            &tmap, l00 + lane * 32, p * CH, b0_, mb);
        }
    }

    // ---------------- persistent mainloop over NC chunks ----------------
    #pragma unroll 1
    for (int g = 0; g < NC; ++g) {
        const int cs = g & (NSTG - 1);
        const int ks = (g >= NCH) ? g - NCH : g;      // g % 18 (ntile<=2)
        const int tl = (g >= NCH) ? cta + GRID : cta;
        const int b  = tl >> 6;
        const int l0 = (tl & 63) * LT;

        mbar_wait(mbar0 + cs * 8, (g >> 2) & 1);      // chunk g landed
        __syncthreads();                              // chunk g-1 fully consumed

        // refill stage (g+3)&3 with chunk g+3 (possibly next tile's)
        if (warp == 0 && g + NSTG - 1 < NC) {
            const int j  = g + NSTG - 1;
            const int jks = (j >= NCH) ? j - NCH : j;
            const int jtl = (j >= NCH) ? cta + GRID : cta;
            uint32_t mb = mbar0 + (j & (NSTG - 1)) * 8;
            if (lane == 0) mbar_expect_tx(mb, CHUNK_TX);
            __syncwarp();
            if (lane < 8)
                tma_load_3d(stg_base + (j & (NSTG - 1)) * STAGE_B + lane * 2048,
                            &tmap, ((jtl & 63) * LT) + lane * 32, jks * CH,
                            jtl >> 6, mb);
        }

        const float* stf = (const float*)(g_sm + cs * STAGE_B);
        const uint2* wf  = g_wfrag + (ks * 8) * 32 + lane;

        #pragma unroll
        for (int s = 0; s < 2; ++s) {
            const int li0 = s * 16 + llo;
            const int a0  = li0 ^ (kc << 2);          // swizzled col, k-even
            const int a1  = li0 ^ ((kc + 1) << 2);    // swizzled col, k-odd
            const int kb  = w512 + kc * 32;

            float vl0 = stf[kb + a0];
            float vl1 = stf[kb + 32 + a1];
            float vl8 = stf[kb + 256 + a0];
            float vl9 = stf[kb + 288 + a1];
            float vh0 = stf[kb + (a0 ^ 8)];
            float vh1 = stf[kb + 32 + (a1 ^ 8)];
            float vh8 = stf[kb + 256 + (a0 ^ 8)];
            float vh9 = stf[kb + 288 + (a1 ^ 8)];

            x2a[s][0] = fmaf(vl0, vl0, x2a[s][0]); x2a[s][0] = fmaf(vl1, vl1, x2a[s][0]);
            x2a[s][0] = fmaf(vl8, vl8, x2a[s][0]); x2a[s][0] = fmaf(vl9, vl9, x2a[s][0]);
            x2a[s][1] = fmaf(vh0, vh0, x2a[s][1]); x2a[s][1] = fmaf(vh1, vh1, x2a[s][1]);
            x2a[s][1] = fmaf(vh8, vh8, x2a[s][1]); x2a[s][1] = fmaf(vh9, vh9, x2a[s][1]);

            uint32_t A0 = packbf(vl0, vl1);
            uint32_t A1 = packbf(vh0, vh1);
            uint32_t A2 = packbf(vl8, vl9);
            uint32_t A3 = packbf(vh8, vh9);

            #pragma unroll
            for (int nt = 0; nt < 8; ++nt) {
                uint2 bb = wf[nt * 32];    // L1-resident
                mma16816(acc[s][nt], A0, A1, A2, A3, bb.x, bb.y);
            }
        }

        // ---- tile boundary: register-only epilogue (overlaps next tile's TMA) ----
        if (ks == NCH - 1) {
            #pragma unroll
            for (int s = 0; s < 2; ++s)
                #pragma unroll
                for (int hh = 0; hh < 2; ++hh) {
                    x2a[s][hh] += __shfl_xor_sync(0xFFFFFFFF, x2a[s][hh], 1);
                    x2a[s][hh] += __shfl_xor_sync(0xFFFFFFFF, x2a[s][hh], 2);
                }

            float* ob = out + ((size_t)b * L_ + l0 + warp * 32) * O_;
            #pragma unroll
            for (int s = 0; s < 2; ++s) {
                float* obs = ob + (size_t)(s * 16) * O_;
                #pragma unroll
                for (int nt = 0; nt < 8; ++nt) {
                    const int o = nt * 8 + kc;
                    float4 wb = g_wb4[nt * 4 + (lane & 3)];
                    float2 r0, r1;
                    r0.x = __expf(-gamma * (x2a[s][0] + wb.x - 2.f * acc[s][nt][0])) + wb.y;
                    r0.y = __expf(-gamma * (x2a[s][0] + wb.z - 2.f * acc[s][nt][1])) + wb.w;
                    r1.x = __expf(-gamma * (x2a[s][1] + wb.x - 2.f * acc[s][nt][2])) + wb.y;
                    r1.y = __expf(-gamma * (x2a[s][1] + wb.z - 2.f * acc[s][nt][3])) + wb.w;
                    *reinterpret_cast<float2*>(obs + (size_t)llo * O_ + o)       = r0;
                    *reinterpret_cast<float2*>(obs + (size_t)(llo + 8) * O_ + o) = r1;
                }
            }

            // reset accumulators for next tile
            #pragma unroll
            for (int s = 0; s < 2; ++s) {
                x2a[s][0] = 0.f; x2a[s][1] = 0.f;
                #pragma unroll
                for (int i = 0; i < 8; ++i)
                    #pragma unroll
                    for (int j = 0; j < 4; ++j) acc[s][i][j] = 0.f;
            }
        }
    }
}

// ---------------- host ----------------
typedef CUresult (CUDAAPI *EncTiledFn)(
    CUtensorMap*, CUtensorMapDataType, cuuint32_t, void*,
    const cuuint64_t*, const cuuint64_t*, const cuuint32_t*, const cuuint32_t*,
    CUtensorMapInterleave, CUtensorMapSwizzle, CUtensorMapL2promotion,
    CUtensorMapFloatOOBfill);

extern "C" void kernel_launch(void* const* d_in, const int* in_sizes, int n_in,
                              void* d_out, int out_size) {
    const float* x     = (const float*)d_in[0];
    const float* w     = (const float*)d_in[1];
    const float* bias  = (const float*)d_in[2];
    const float* gamma = (const float*)d_in[3];
    float* out = (float*)d_out;

    static EncTiledFn enc = nullptr;
    if (!enc) {
        cudaDriverEntryPointQueryResult qr;
#if CUDART_VERSION >= 12050
        cudaGetDriverEntryPointByVersion("cuTensorMapEncodeTiled", (void**)&enc,
                                         12000, cudaEnableDefault, &qr);
#else
        cudaGetDriverEntryPoint("cuTensorMapEncodeTiled", (void**)&enc,
                                cudaEnableDefault, &qr);
#endif
    }

    CUtensorMap tmap;
    cuuint64_t dims[3]    = {(cuuint64_t)L_, (cuuint64_t)K_, (cuuint64_t)B_};
    cuuint64_t strides[2] = {(cuuint64_t)L_ * 4, (cuuint64_t)K_ * L_ * 4};
    cuuint32_t box[3]     = {32, CH, 1};
    cuuint32_t estr[3]    = {1, 1, 1};
    enc(&tmap, CU_TENSOR_MAP_DATA_TYPE_FLOAT32, 3, (void*)x,
        dims, strides, box, estr,
        CU_TENSOR_MAP_INTERLEAVE_NONE, CU_TENSOR_MAP_SWIZZLE_128B,
        CU_TENSOR_MAP_L2_PROMOTION_L2_128B, CU_TENSOR_MAP_FLOAT_OOB_FILL_NONE);

    cudaFuncSetAttribute(gauss_main_kernel,
                         cudaFuncAttributeMaxDynamicSharedMemorySize, SMEM_BYTES);

    gauss_prep_kernel<<<NKS + 1, NT>>>(w, bias);
    gauss_main_kernel<<<GRID, NT, SMEM_BYTES>>>(tmap, gamma, out);
    (void)in_sizes; (void)n_in; (void)out_size;
}

// round 16
// speedup vs baseline: 1.1244x; 1.1244x over previous
#include <cuda_runtime.h>
#include <cuda.h>
#include <cuda_bf16.h>
#include <cstdint>

// ---------------- problem constants ----------------
#define B_   8
#define K_   288
#define L_   16384
#define O_   64
#define NT   256
#define LT   256         // l-tile per CTA
#define CH   16          // k per chunk = one k-step
#define NCH  18
#define NSTG 4

#define STAGE_B   16384                     // 8 segs x 16 k-rows x 128B (swizzled)
#define CHUNK_TX  16384
#define OFF_MBAR  (NSTG * STAGE_B)          // 65536
#define OFF_WF    (OFF_MBAR + 64)           // 65600: wfrag [18][8][32] uint2
#define WF_BYTES  (NCH * 8 * 32 * 8)        // 36864
#define OFF_WB    (OFF_WF + WF_BYTES)       // 102464: wb4 [32] float4
#define SMEM_BYTES (OFF_WB + 512)           // 102976 (x2 CTAs = 205952 <= 227KB)

// ---------------- PTX helpers ----------------
__device__ __forceinline__ uint32_t smem_u32(const void* p) {
    return (uint32_t)__cvta_generic_to_shared(p);
}
__device__ __forceinline__ void mbar_init(uint32_t mbar, uint32_t cnt) {
    asm volatile("mbarrier.init.shared.b64 [%0], %1;" :: "r"(mbar), "r"(cnt) : "memory");
}
__device__ __forceinline__ void mbar_expect_tx(uint32_t mbar, uint32_t bytes) {
    asm volatile("mbarrier.arrive.expect_tx.shared.b64 _, [%0], %1;"
                 :: "r"(mbar), "r"(bytes) : "memory");
}
__device__ __forceinline__ void mbar_wait(uint32_t mbar, uint32_t parity) {
    uint32_t done;
    asm volatile(
        "{\n\t.reg .pred p;\n\t"
        "mbarrier.try_wait.parity.acquire.cta.shared::cta.b64 p, [%1], %2;\n\t"
        "selp.b32 %0, 1, 0, p;\n\t}"
        : "=r"(done) : "r"(mbar), "r"(parity) : "memory");
    if (!done) {
        asm volatile(
            "{\n\t.reg .pred P1;\n\t"
            "WAIT_LOOP_%=:\n\t"
            "mbarrier.try_wait.parity.acquire.cta.shared::cta.b64 P1, [%0], %1, 0x989680;\n\t"
            "@P1 bra.uni WAIT_DONE_%=;\n\t"
            "bra.uni WAIT_LOOP_%=;\n\t"
            "WAIT_DONE_%=:\n\t}"
            :: "r"(mbar), "r"(parity) : "memory");
    }
}
__device__ __forceinline__ void tma_load_3d(uint32_t dst, const CUtensorMap* tmap,
                                            int cx, int cy, int cz, uint32_t mbar) {
    asm volatile(
        "cp.async.bulk.tensor.3d.shared::cta.global.tile.mbarrier::complete_tx::bytes "
        "[%0], [%1, {%2, %3, %4}], [%5];"
        :: "r"(dst), "l"(tmap), "r"(cx), "r"(cy), "r"(cz), "r"(mbar) : "memory");
}
__device__ __forceinline__ uint32_t packbf(float lo, float hi) {
    __nv_bfloat162 h = __floats2bfloat162_rn(lo, hi);
    return *reinterpret_cast<uint32_t*>(&h);
}
__device__ __forceinline__ void mma16816(float* c,
                                         uint32_t a0, uint32_t a1, uint32_t a2, uint32_t a3,
                                         uint32_t b0, uint32_t b1) {
    asm volatile(
        "mma.sync.aligned.m16n8k16.row.col.f32.bf16.bf16.f32 "
        "{%0,%1,%2,%3}, {%4,%5,%6,%7}, {%8,%9}, {%0,%1,%2,%3};"
        : "+f"(c[0]), "+f"(c[1]), "+f"(c[2]), "+f"(c[3])
        : "r"(a0), "r"(a1), "r"(a2), "r"(a3), "r"(b0), "r"(b1));
}

extern __shared__ __align__(1024) char g_sm[];

__global__ __launch_bounds__(NT, 2)
void gauss_main_kernel(const __grid_constant__ CUtensorMap tmap,
                       const float* __restrict__ w,
                       const float* __restrict__ bias,
                       const float* __restrict__ gamma_p,
                       float* __restrict__ out) {
    const int t    = threadIdx.x;
    const int warp = t >> 5;
    const int lane = t & 31;
    const int bx   = blockIdx.x;
    const int b    = bx >> 6;              // 64 l-tiles per batch
    const int l0   = (bx & 63) * LT;

    const uint32_t stg_base = smem_u32(g_sm);
    const uint32_t mbar0    = stg_base + OFF_MBAR;
    uint2*  s_wfrag = (uint2*)(g_sm + OFF_WF);
    float4* s_wb4   = (float4*)(g_sm + OFF_WB);
    float*  s_w2t   = (float*)(g_sm + 3 * STAGE_B);   // temp: stage 3 idle until c=0 refill

    const int kc  = (lane & 3) * 2;
    const int llo = lane >> 2;
    const int w512 = warp * 512;           // warp's seg slice (floats) per stage

    if (t == 0) {
        #pragma unroll
        for (int s = 0; s < NSTG; ++s) mbar_init(mbar0 + s * 8, 1);
    }
    __syncthreads();

    // prologue TMA first: chunks 0..2 in flight while we build weight tables
    if (warp == 0) {
        #pragma unroll
        for (int p = 0; p < NSTG - 1; ++p) {
            uint32_t mb = mbar0 + p * 8;
            if (lane == 0) mbar_expect_tx(mb, CHUNK_TX);
            __syncwarp();
            if (lane < 8)
                tma_load_3d(stg_base + p * STAGE_B + lane * 2048,
                            &tmap, l0 + lane * 32, p * CH, b, mb);
        }
    }

    // ---- in-CTA weight prep (overlaps prologue TMA) ----
    // B fragments: 4608 uint2 entries, 18 per thread (w is L2-resident)
    #pragma unroll
    for (int i = 0; i < NCH; ++i) {
        int idx = i * NT + t;              // 0..4607
        int ks  = idx >> 8;
        int nt  = (idx >> 5) & 7;
        int ln  = idx & 31;
        int k = ks * 16 + (ln & 3) * 2;
        int o = nt * 8 + (ln >> 2);
        __nv_bfloat162 b0 = __floats2bfloat162_rn(w[k * O_ + o], w[(k + 1) * O_ + o]);
        __nv_bfloat162 b1 = __floats2bfloat162_rn(w[(k + 8) * O_ + o], w[(k + 9) * O_ + o]);
        uint2 v;
        v.x = *reinterpret_cast<uint32_t*>(&b0);
        v.y = *reinterpret_cast<uint32_t*>(&b1);
        s_wfrag[idx] = v;
    }
    // w2 (fp32): 4 threads per o, shfl-combine within quad
    {
        int o   = t >> 2;
        int sub = t & 3;
        float s = 0.f;
        #pragma unroll 8
        for (int k = sub; k < K_; k += 4) { float v = w[k * O_ + o]; s = fmaf(v, v, s); }
        s += __shfl_xor_sync(0xFFFFFFFF, s, 1);
        s += __shfl_xor_sync(0xFFFFFFFF, s, 2);
        if (sub == 0) s_w2t[o] = s;
    }
    __syncthreads();
    if (t < O_ / 2) {
        float4 r;
        r.x = s_w2t[2 * t];     r.y = bias[2 * t];
        r.z = s_w2t[2 * t + 1]; r.w = bias[2 * t + 1];
        s_wb4[t] = r;
    }
    // (no extra sync needed: mainloop's first __syncthreads orders s_wb4 before use;
    //  s_w2t lives in stage 3, whose refill is issued only after that sync)

    float acc[2][8][4];
    #pragma unroll
    for (int s = 0; s < 2; ++s)
        #pragma unroll
        for (int i = 0; i < 8; ++i)
            #pragma unroll
            for (int j = 0; j < 4; ++j) acc[s][i][j] = 0.f;
    float x2a[2][2] = {{0.f, 0.f}, {0.f, 0.f}};

    // ---------------- mainloop over 18 chunks ----------------
    #pragma unroll 1
    for (int c = 0; c < NCH; ++c) {
        const int cs = c & (NSTG - 1);
        mbar_wait(mbar0 + cs * 8, (c >> 2) & 1);     // chunk c landed
        __syncthreads();                   // all warps past chunk c-1's reads (+prep done)

        // refill stage (c+3)&3 with chunk c+3
        if (warp == 0 && c + NSTG - 1 < NCH) {
            const int j = c + NSTG - 1;
            uint32_t mb = mbar0 + (j & (NSTG - 1)) * 8;
            if (lane == 0) mbar_expect_tx(mb, CHUNK_TX);
            __syncwarp();
            if (lane < 8)
                tma_load_3d(stg_base + (j & (NSTG - 1)) * STAGE_B + lane * 2048,
                            &tmap, l0 + lane * 32, j * CH, b, mb);
        }

        const float* stf = (const float*)(g_sm + cs * STAGE_B);
        const uint2* wf  = s_wfrag + (c * 8) * 32 + lane;

        #pragma unroll
        for (int s = 0; s < 2; ++s) {
            const int li0 = s * 16 + llo;
            const int a0  = li0 ^ (kc << 2);          // swizzled col, k-even
            const int a1  = li0 ^ ((kc + 1) << 2);    // swizzled col, k-odd
            const int kb  = w512 + kc * 32;

            float vl0 = stf[kb + a0];
            float vl1 = stf[kb + 32 + a1];
            float vl8 = stf[kb + 256 + a0];
            float vl9 = stf[kb + 288 + a1];
            float vh0 = stf[kb + (a0 ^ 8)];
            float vh1 = stf[kb + 32 + (a1 ^ 8)];
            float vh8 = stf[kb + 256 + (a0 ^ 8)];
            float vh9 = stf[kb + 288 + (a1 ^ 8)];

            x2a[s][0] = fmaf(vl0, vl0, x2a[s][0]); x2a[s][0] = fmaf(vl1, vl1, x2a[s][0]);
            x2a[s][0] = fmaf(vl8, vl8, x2a[s][0]); x2a[s][0] = fmaf(vl9, vl9, x2a[s][0]);
            x2a[s][1] = fmaf(vh0, vh0, x2a[s][1]); x2a[s][1] = fmaf(vh1, vh1, x2a[s][1]);
            x2a[s][1] = fmaf(vh8, vh8, x2a[s][1]); x2a[s][1] = fmaf(vh9, vh9, x2a[s][1]);

            uint32_t A0 = packbf(vl0, vl1);
            uint32_t A1 = packbf(vh0, vh1);
            uint32_t A2 = packbf(vl8, vl9);
            uint32_t A3 = packbf(vh8, vh9);

            #pragma unroll
            for (int nt = 0; nt < 8; ++nt) {
                uint2 bb = wf[nt * 32];    // conflict-free LDS.64
                mma16816(acc[s][nt], A0, A1, A2, A3, bb.x, bb.y);
            }
        }
    }

    // x2 reduction across the 4 lanes sharing each l row
    #pragma unroll
    for (int s = 0; s < 2; ++s)
        #pragma unroll
        for (int hh = 0; hh < 2; ++hh) {
            x2a[s][hh] += __shfl_xor_sync(0xFFFFFFFF, x2a[s][hh], 1);
            x2a[s][hh] += __shfl_xor_sync(0xFFFFFFFF, x2a[s][hh], 2);
        }

    // ---------------- register epilogue ----------------
    const float gamma = __ldg(gamma_p);
    float* ob = out + ((size_t)b * L_ + l0 + warp * 32) * O_;

    #pragma unroll
    for (int s = 0; s < 2; ++s) {
        float* obs = ob + (size_t)(s * 16) * O_;
        #pragma unroll
        for (int nt = 0; nt < 8; ++nt) {
            const int o = nt * 8 + kc;
            float4 wb = s_wb4[nt * 4 + (lane & 3)];
            float2 r0, r1;
            r0.x = __expf(-gamma * (x2a[s][0] + wb.x - 2.f * acc[s][nt][0])) + wb.y;
            r0.y = __expf(-gamma * (x2a[s][0] + wb.z - 2.f * acc[s][nt][1])) + wb.w;
            r1.x = __expf(-gamma * (x2a[s][1] + wb.x - 2.f * acc[s][nt][2])) + wb.y;
            r1.y = __expf(-gamma * (x2a[s][1] + wb.z - 2.f * acc[s][nt][3])) + wb.w;
            *reinterpret_cast<float2*>(obs + (size_t)llo * O_ + o)       = r0;
            *reinterpret_cast<float2*>(obs + (size_t)(llo + 8) * O_ + o) = r1;
        }
    }
}

// ---------------- host ----------------
typedef CUresult (CUDAAPI *EncTiledFn)(
    CUtensorMap*, CUtensorMapDataType, cuuint32_t, void*,
    const cuuint64_t*, const cuuint64_t*, const cuuint32_t*, const cuuint32_t*,
    CUtensorMapInterleave, CUtensorMapSwizzle, CUtensorMapL2promotion,
    CUtensorMapFloatOOBfill);

extern "C" void kernel_launch(void* const* d_in, const int* in_sizes, int n_in,
                              void* d_out, int out_size) {
    const float* x     = (const float*)d_in[0];
    const float* w     = (const float*)d_in[1];
    const float* bias  = (const float*)d_in[2];
    const float* gamma = (const float*)d_in[3];
    float* out = (float*)d_out;

    static EncTiledFn enc = nullptr;
    if (!enc) {
        cudaDriverEntryPointQueryResult qr;
#if CUDART_VERSION >= 12050
        cudaGetDriverEntryPointByVersion("cuTensorMapEncodeTiled", (void**)&enc,
                                         12000, cudaEnableDefault, &qr);
#else
        cudaGetDriverEntryPoint("cuTensorMapEncodeTiled", (void**)&enc,
                                cudaEnableDefault, &qr);
#endif
    }

    CUtensorMap tmap;
    cuuint64_t dims[3]    = {(cuuint64_t)L_, (cuuint64_t)K_, (cuuint64_t)B_};
    cuuint64_t strides[2] = {(cuuint64_t)L_ * 4, (cuuint64_t)K_ * L_ * 4};
    cuuint32_t box[3]     = {32, CH, 1};
    cuuint32_t estr[3]    = {1, 1, 1};
    enc(&tmap, CU_TENSOR_MAP_DATA_TYPE_FLOAT32, 3, (void*)x,
        dims, strides, box, estr,
        CU_TENSOR_MAP_INTERLEAVE_NONE, CU_TENSOR_MAP_SWIZZLE_128B,
        CU_TENSOR_MAP_L2_PROMOTION_L2_128B, CU_TENSOR_MAP_FLOAT_OOB_FILL_NONE);

    cudaFuncSetAttribute(gauss_main_kernel,
                         cudaFuncAttributeMaxDynamicSharedMemorySize, SMEM_BYTES);

    gauss_main_kernel<<<B_ * (L_ / LT), NT, SMEM_BYTES>>>(tmap, w, bias, gamma, out);
    (void)in_sizes; (void)n_in; (void)out_size;
}